// round 1
// baseline (speedup 1.0000x reference)
#include <cuda_runtime.h>
#include <cuda_bf16.h>
#include <cstdint>

// ---------------- problem constants ----------------
#define NN 40000      // nodes
#define EE 640000     // edges
#define CD 128        // channels (= IN = H*D)
#define HH 8          // heads
#define DD 16         // dim per head
#define EDD 64        // edge feature dim
#define C2 256        // FFN hidden
#define EPS 1e-5f

// ---------------- scratch (static device globals; no allocs allowed) ----------------
__device__ float    g_qd[(size_t)NN * CD];
__device__ float    g_kd[(size_t)NN * CD];
__device__ float    g_vd[(size_t)NN * CD];
__device__ float    g_eb[(size_t)EE * HH];    // per-edge bias
__device__ float    g_sc[(size_t)EE * HH];    // scores, then exp(scores - max)
__device__ unsigned g_smax[(size_t)NN * HH];  // ordered-uint encoded max
__device__ float    g_den[(size_t)NN * HH];
__device__ float    g_agg[(size_t)NN * CD];
__device__ float    g_rst[(size_t)NN * CD];
__device__ float    g_h1[(size_t)NN * C2];
__device__ float    g_h2[(size_t)NN * CD];
__device__ float    g_stats[4 * CD];          // [sum1, sq1, sum2, sq2]

// ---------------- helpers ----------------
__device__ __forceinline__ unsigned ordEnc(float f) {
    unsigned b = __float_as_uint(f);
    return (b & 0x80000000u) ? ~b : (b | 0x80000000u);
}
__device__ __forceinline__ float ordDec(unsigned u) {
    unsigned b = (u & 0x80000000u) ? (u ^ 0x80000000u) : ~u;
    return __uint_as_float(b);
}

// ---------------- init: zero accumulators every call (graph replays!) ----------------
__global__ void init_kernel() {
    int i = blockIdx.x * blockDim.x + threadIdx.x;
    int stride = gridDim.x * blockDim.x;
    for (int j = i; j < NN * CD; j += stride) g_agg[j] = 0.f;
    for (int j = i; j < NN * HH; j += stride) {
        g_den[j] = 0.f;
        g_smax[j] = 0x007FFFFFu;  // ordEnc(-inf)
    }
    if (i < 4 * CD) g_stats[i] = 0.f;
}

// ---------------- SGEMM: Y[M,Co] = X[M,K] @ W[Co,K]^T (+bias)(+res)(relu) ----------------
// BM=BN=64, BK=16, TM=TN=4, 256 threads. M%64==0, K%16==0, Co%64==0 for our shapes.
template <bool RELU, bool BIAS, bool RES>
__global__ void __launch_bounds__(256)
sgemm_kernel(const float* __restrict__ X, const float* __restrict__ W,
             const float* __restrict__ bias, const float* __restrict__ res,
             float* __restrict__ Y, int M, int K, int Co) {
    __shared__ float Xs[16][64];
    __shared__ float Ws[16][64];
    const int t = threadIdx.x;
    const int bm = blockIdx.x * 64;
    const int bn = blockIdx.y * 64;
    const int ty = t >> 4;        // 0..15 (row group)
    const int tx = t & 15;        // 0..15 (col group)
    const int lrow = t >> 2;      // 0..63 (load row)
    const int lk4  = (t & 3) * 4; // 0,4,8,12 (load k offset)

    float acc[4][4] = {};
    const float* Xg = X + (size_t)(bm + lrow) * K + lk4;
    const float* Wg = W + (size_t)(bn + lrow) * K + lk4;

    for (int k0 = 0; k0 < K; k0 += 16) {
        float4 xv = *(const float4*)(Xg + k0);
        float4 wv = *(const float4*)(Wg + k0);
        __syncthreads();
        Xs[lk4 + 0][lrow] = xv.x; Xs[lk4 + 1][lrow] = xv.y;
        Xs[lk4 + 2][lrow] = xv.z; Xs[lk4 + 3][lrow] = xv.w;
        Ws[lk4 + 0][lrow] = wv.x; Ws[lk4 + 1][lrow] = wv.y;
        Ws[lk4 + 2][lrow] = wv.z; Ws[lk4 + 3][lrow] = wv.w;
        __syncthreads();
#pragma unroll
        for (int k = 0; k < 16; k++) {
            float4 a = *(const float4*)&Xs[k][ty * 4];
            float4 b = *(const float4*)&Ws[k][tx * 4];
            acc[0][0] += a.x * b.x; acc[0][1] += a.x * b.y; acc[0][2] += a.x * b.z; acc[0][3] += a.x * b.w;
            acc[1][0] += a.y * b.x; acc[1][1] += a.y * b.y; acc[1][2] += a.y * b.z; acc[1][3] += a.y * b.w;
            acc[2][0] += a.z * b.x; acc[2][1] += a.z * b.y; acc[2][2] += a.z * b.z; acc[2][3] += a.z * b.w;
            acc[3][0] += a.w * b.x; acc[3][1] += a.w * b.y; acc[3][2] += a.w * b.z; acc[3][3] += a.w * b.w;
        }
    }

    const int n0 = bn + tx * 4;
    float4 bb = make_float4(0.f, 0.f, 0.f, 0.f);
    if (BIAS) bb = *(const float4*)&bias[n0];
#pragma unroll
    for (int i = 0; i < 4; i++) {
        const int m = bm + ty * 4 + i;
        float4 o = make_float4(acc[i][0], acc[i][1], acc[i][2], acc[i][3]);
        if (BIAS) { o.x += bb.x; o.y += bb.y; o.z += bb.z; o.w += bb.w; }
        if (RELU) { o.x = fmaxf(o.x, 0.f); o.y = fmaxf(o.y, 0.f); o.z = fmaxf(o.z, 0.f); o.w = fmaxf(o.w, 0.f); }
        if (RES) {
            float4 r = *(const float4*)&res[(size_t)m * Co + n0];
            o.x += r.x; o.y += r.y; o.z += r.z; o.w += r.w;
        }
        *(float4*)&Y[(size_t)m * Co + n0] = o;
    }
}

// ---------------- edge bias: g_eb[e,h] = edge_feat[e,:] . We[h,:] + be[h] ----------------
__global__ void __launch_bounds__(256)
eb_kernel(const float* __restrict__ ef, const float* __restrict__ We,
          const float* __restrict__ be) {
    __shared__ float sWe[HH * EDD];
    __shared__ float sbe[HH];
    for (int i = threadIdx.x; i < HH * EDD; i += 256) sWe[i] = We[i];
    if (threadIdx.x < HH) sbe[threadIdx.x] = be[threadIdx.x];
    __syncthreads();

    const int e = blockIdx.x * 256 + threadIdx.x;  // EE % 256 == 0
    const float4* efp = (const float4*)(ef + (size_t)e * EDD);
    float acc[HH];
#pragma unroll
    for (int h = 0; h < HH; h++) acc[h] = sbe[h];
#pragma unroll
    for (int j4 = 0; j4 < EDD / 4; j4++) {
        float4 v = efp[j4];
#pragma unroll
        for (int h = 0; h < HH; h++) {
            float4 w = *(const float4*)&sWe[h * EDD + j4 * 4];
            acc[h] += v.x * w.x + v.y * w.y + v.z * w.z + v.w * w.w;
        }
    }
    float4 o0 = make_float4(acc[0], acc[1], acc[2], acc[3]);
    float4 o1 = make_float4(acc[4], acc[5], acc[6], acc[7]);
    ((float4*)g_eb)[(size_t)e * 2 + 0] = o0;
    ((float4*)g_eb)[(size_t)e * 2 + 1] = o1;
}

// ---------------- scores + segment max (warp per edge) ----------------
__global__ void __launch_bounds__(256)
score_kernel(const int* __restrict__ src, const int* __restrict__ dst) {
    const int warpId = (blockIdx.x * 256 + threadIdx.x) >> 5;
    const int lane = threadIdx.x & 31;
    if (warpId >= EE) return;
    const int e = warpId;
    const int s = __ldg(&src[e]);
    const int d = __ldg(&dst[e]);
    float4 qv = ((const float4*)g_qd)[(size_t)d * 32 + lane];
    float4 kv = ((const float4*)g_kd)[(size_t)s * 32 + lane];
    float p = qv.x * kv.x + qv.y * kv.y + qv.z * kv.z + qv.w * kv.w;
    p += __shfl_xor_sync(0xffffffffu, p, 1);
    p += __shfl_xor_sync(0xffffffffu, p, 2);
    if ((lane & 3) == 0) {
        const int h = lane >> 2;
        float sc = p * 0.25f + g_eb[(size_t)e * HH + h];  // 1/sqrt(16)
        g_sc[(size_t)e * HH + h] = sc;
        atomicMax(&g_smax[(size_t)d * HH + h], ordEnc(sc));
    }
}

// ---------------- exp + segment denom ----------------
__global__ void __launch_bounds__(256)
exp_kernel(const int* __restrict__ dst) {
    const int i = blockIdx.x * 256 + threadIdx.x;  // EE*HH % 256 == 0
    const int e = i >> 3, h = i & 7;
    const int d = __ldg(&dst[e]);
    const float m = ordDec(g_smax[(size_t)d * HH + h]);
    const float ex = __expf(g_sc[i] - m);
    g_sc[i] = ex;
    atomicAdd(&g_den[(size_t)d * HH + h], ex);
}

// ---------------- weighted scatter aggregation (warp per edge, vector red) ----------------
__global__ void __launch_bounds__(256)
agg_kernel(const int* __restrict__ src, const int* __restrict__ dst) {
    const int warpId = (blockIdx.x * 256 + threadIdx.x) >> 5;
    const int lane = threadIdx.x & 31;
    if (warpId >= EE) return;
    const int e = warpId;
    const int s = __ldg(&src[e]);
    const int d = __ldg(&dst[e]);
    const int h = lane >> 2;
    const float a = g_sc[(size_t)e * HH + h] / g_den[(size_t)d * HH + h];
    float4 vv = ((const float4*)g_vd)[(size_t)s * 32 + lane];
    float* p = g_agg + (size_t)d * CD + lane * 4;
    asm volatile("red.global.add.v4.f32 [%0], {%1,%2,%3,%4};"
                 :: "l"(p), "f"(vv.x * a), "f"(vv.y * a), "f"(vv.z * a), "f"(vv.w * a)
                 : "memory");
}

// ---------------- batchnorm stats (column sums / sumsq) ----------------
__global__ void __launch_bounds__(128)
bn_stats_kernel(const float* __restrict__ X, float* __restrict__ sums) {
    const int c = threadIdx.x;  // 128 columns
    const int r0 = blockIdx.x * 256;
    const int rend = min(r0 + 256, NN);
    float s = 0.f, s2 = 0.f;
    for (int r = r0; r < rend; r++) {
        float v = X[(size_t)r * CD + c];
        s += v; s2 += v * v;
    }
    atomicAdd(&sums[c], s);
    atomicAdd(&sums[CD + c], s2);
}

// ---------------- batchnorm apply ----------------
__global__ void __launch_bounds__(256)
bn_apply_kernel(const float* __restrict__ X, float* __restrict__ Y,
                const float* __restrict__ sums,
                const float* __restrict__ g, const float* __restrict__ b) {
    const int i = blockIdx.x * 256 + threadIdx.x;  // NN*CD % 256 == 0
    const int c = i & (CD - 1);
    const float inv = 1.f / (float)NN;
    const float mu = sums[c] * inv;
    const float var = sums[CD + c] * inv - mu * mu;
    const float rs = rsqrtf(var + EPS);
    Y[i] = (X[i] - mu) * rs * g[c] + b[c];
}

// ---------------- launcher ----------------
extern "C" void kernel_launch(void* const* d_in, const int* in_sizes, int n_in,
                              void* d_out, int out_size) {
    const float* q   = (const float*)d_in[0];
    const float* k   = (const float*)d_in[1];
    const float* v   = (const float*)d_in[2];
    const float* ef  = (const float*)d_in[3];
    const int*   src = (const int*)d_in[4];
    const int*   dst = (const int*)d_in[5];
    const float* Wq  = (const float*)d_in[6];
    const float* Wk  = (const float*)d_in[7];
    const float* Wv  = (const float*)d_in[8];
    const float* We  = (const float*)d_in[9];
    const float* be  = (const float*)d_in[10];
    const float* Wo  = (const float*)d_in[11];
    const float* W1  = (const float*)d_in[12];
    const float* b1  = (const float*)d_in[13];
    const float* W2  = (const float*)d_in[14];
    const float* b2  = (const float*)d_in[15];
    const float* g1  = (const float*)d_in[16];
    const float* bt1 = (const float*)d_in[17];
    const float* g2  = (const float*)d_in[18];
    const float* bt2 = (const float*)d_in[19];
    float* out = (float*)d_out;

    float* p_qd; cudaGetSymbolAddress((void**)&p_qd, g_qd);
    float* p_kd; cudaGetSymbolAddress((void**)&p_kd, g_kd);
    float* p_vd; cudaGetSymbolAddress((void**)&p_vd, g_vd);
    float* p_agg; cudaGetSymbolAddress((void**)&p_agg, g_agg);
    float* p_rst; cudaGetSymbolAddress((void**)&p_rst, g_rst);
    float* p_h1; cudaGetSymbolAddress((void**)&p_h1, g_h1);
    float* p_h2; cudaGetSymbolAddress((void**)&p_h2, g_h2);
    float* p_stats; cudaGetSymbolAddress((void**)&p_stats, g_stats);

    init_kernel<<<8192, 256>>>();

    // projections
    sgemm_kernel<false, false, false><<<dim3(NN / 64, CD / 64), 256>>>(q, Wq, nullptr, nullptr, p_qd, NN, CD, CD);
    sgemm_kernel<false, false, false><<<dim3(NN / 64, CD / 64), 256>>>(k, Wk, nullptr, nullptr, p_kd, NN, CD, CD);
    sgemm_kernel<false, false, false><<<dim3(NN / 64, CD / 64), 256>>>(v, Wv, nullptr, nullptr, p_vd, NN, CD, CD);

    // edge phase
    eb_kernel<<<EE / 256, 256>>>(ef, We, be);
    score_kernel<<<EE / 8, 256>>>(src, dst);
    exp_kernel<<<EE * HH / 256, 256>>>(dst);
    agg_kernel<<<EE / 8, 256>>>(src, dst);

    // out proj + residual, BN1
    sgemm_kernel<false, false, true><<<dim3(NN / 64, CD / 64), 256>>>(p_agg, Wo, nullptr, q, p_rst, NN, CD, CD);
    bn_stats_kernel<<<(NN + 255) / 256, 128>>>(p_rst, p_stats);
    bn_apply_kernel<<<NN * CD / 256, 256>>>(p_rst, p_rst, p_stats, g1, bt1);

    // FFN + residual, BN2
    sgemm_kernel<true, true, false><<<dim3(NN / 64, C2 / 64), 256>>>(p_rst, W1, b1, nullptr, p_h1, NN, CD, C2);
    sgemm_kernel<false, true, true><<<dim3(NN / 64, CD / 64), 256>>>(p_h1, W2, b2, p_rst, p_h2, NN, C2, CD);
    bn_stats_kernel<<<(NN + 255) / 256, 128>>>(p_h2, p_stats + 2 * CD);
    bn_apply_kernel<<<NN * CD / 256, 256>>>(p_h2, out, p_stats + 2 * CD, g2, bt2);
}